// round 8
// baseline (speedup 1.0000x reference)
#include <cuda_runtime.h>
#include <cuda_bf16.h>
#include <cstdint>

#define BB 2
#define PP 32768
#define VV 5023
#define LAT 32
#define HID 128
#define NPTS (BB*PP)
#define NSUB 9
#define ROWB 272          // bytes per activation row (128 bf16 + 8B pad -> conflict-free ldmatrix)

// Weight fragments, uint4-paired: [s][h][ks][np][lane], uint4 = frags (nt=2np | nt=2np+1)
__device__ uint4 g_wfrag[NSUB * 2 * 8 * 8 * 32];
__device__ float g_gshift[NPTS * 3];

// ---------------------------------------------------------------------------
__global__ void prep_wfrag(const float* w0, const float* w1, const float* w2,
                           const float* w3, const float* w4, const float* w5,
                           const float* w6, const float* w7) {
    int idx = blockIdx.x * blockDim.x + threadIdx.x;
    if (idx >= NSUB * 2 * 8 * 8 * 32) return;
    int lane = idx & 31;
    int np = (idx >> 5) & 7;
    int ks = (idx >> 8) & 7;
    int h  = (idx >> 11) & 1;
    int s  = idx >> 12;

    const float* w; int Ktot, k0, valid;
    switch (s) {
        case 0: w = w0; Ktot = 110; k0 = 0;   valid = 110; break;
        case 1: w = w1; Ktot = 128; k0 = 0;   valid = 128; break;
        case 2: w = w2; Ktot = 128; k0 = 0;   valid = 128; break;
        case 3: w = w3; Ktot = 128; k0 = 0;   valid = 128; break;
        case 4: w = w4; Ktot = 238; k0 = 0;   valid = 110; break;   // l4 init part
        case 5: w = w4; Ktot = 238; k0 = 110; valid = 128; break;   // l4 hidden part
        case 6: w = w5; Ktot = 128; k0 = 0;   valid = 128; break;
        case 7: w = w6; Ktot = 128; k0 = 0;   valid = 128; break;
        default: w = w7; Ktot = 128; k0 = 0;  valid = 128; break;
    }
    uint32_t frag[2][2];
#pragma unroll
    for (int d = 0; d < 2; ++d) {
        int nt = 2 * np + d;
        int n = nt * 8 + (lane >> 2);
        int kb = ks * 16 + (lane & 3) * 2;
        unsigned short v16[4];
#pragma unroll
        for (int j = 0; j < 4; ++j) {
            int kk = kb + (j & 1) + (j >> 1) * 8;
            float v = (kk < valid) ? w[n * Ktot + k0 + kk] : 0.f;
            __nv_bfloat16 hi = __float2bfloat16_rn(v);
            __nv_bfloat16 r = (h == 0) ? hi : __float2bfloat16_rn(v - __bfloat162float(hi));
            v16[j] = __bfloat16_as_ushort(r);
        }
        frag[d][0] = (uint32_t)v16[0] | ((uint32_t)v16[1] << 16);
        frag[d][1] = (uint32_t)v16[2] | ((uint32_t)v16[3] << 16);
    }
    g_wfrag[idx] = make_uint4(frag[0][0], frag[0][1], frag[1][0], frag[1][1]);
}

// ---------------------------------------------------------------------------
// NN search + gshift (unchanged)
// ---------------------------------------------------------------------------
__global__ void nn_kernel(const float* __restrict__ pts,
                          const float* __restrict__ deformed,
                          const float* __restrict__ cano) {
    extern __shared__ float4 sv[];
    const int blockBase = blockIdx.x * 512;
    const int b = blockBase / PP;
    const float* dv = deformed + (size_t)b * VV * 3;
    for (int v = threadIdx.x; v < VV; v += 256) {
        float x = dv[3 * v + 0], y = dv[3 * v + 1], z = dv[3 * v + 2];
        sv[v] = make_float4(x, y, z, 0.5f * (x * x + y * y + z * z));
    }
    __syncthreads();
    const int pA = blockBase + threadIdx.x;
    const int pB = pA + 256;
    float ax = pts[pA * 3 + 0], ay = pts[pA * 3 + 1], az = pts[pA * 3 + 2];
    float bx = pts[pB * 3 + 0], by = pts[pB * 3 + 1], bz = pts[pB * 3 + 2];
    float bsA = 3.4e38f, bsB = 3.4e38f;
    int iA = 0, iB = 0;
#pragma unroll 4
    for (int v = 0; v < VV; ++v) {
        float4 q = sv[v];
        float sA = fmaf(-q.x, ax, fmaf(-q.y, ay, fmaf(-q.z, az, q.w)));
        float sB = fmaf(-q.x, bx, fmaf(-q.y, by, fmaf(-q.z, bz, q.w)));
        if (sA < bsA) { bsA = sA; iA = v; }
        if (sB < bsB) { bsB = sB; iB = v; }
    }
    {
        float p2 = fmaf(ax, ax, fmaf(ay, ay, az * az));
        float w = __expf(-fmaxf(fmaf(2.f, bsA, p2), 0.f));
        float4 q = sv[iA];
        g_gshift[pA * 3 + 0] = (cano[iA * 3 + 0] - q.x) * w;
        g_gshift[pA * 3 + 1] = (cano[iA * 3 + 1] - q.y) * w;
        g_gshift[pA * 3 + 2] = (cano[iA * 3 + 2] - q.z) * w;
    }
    {
        float p2 = fmaf(bx, bx, fmaf(by, by, bz * bz));
        float w = __expf(-fmaxf(fmaf(2.f, bsB, p2), 0.f));
        float4 q = sv[iB];
        g_gshift[pB * 3 + 0] = (cano[iB * 3 + 0] - q.x) * w;
        g_gshift[pB * 3 + 1] = (cano[iB * 3 + 1] - q.y) * w;
        g_gshift[pB * 3 + 2] = (cano[iB * 3 + 2] - q.z) * w;
    }
}

// ---------------------------------------------------------------------------
// helpers
// ---------------------------------------------------------------------------
__device__ __forceinline__ uint32_t smem_u32(const void* p) {
    uint32_t a;
    asm("{ .reg .u64 t; cvta.to.shared.u64 t, %1; cvt.u32.u64 %0, t; }" : "=r"(a) : "l"(p));
    return a;
}
#define CP_ASYNC16(dst, src) \
    asm volatile("cp.async.cg.shared.global [%0], [%1], 16;" :: "r"(dst), "l"(src))
#define CP_COMMIT() asm volatile("cp.async.commit_group;" ::: "memory")
#define CP_WAIT0()  asm volatile("cp.async.wait_group 0;" ::: "memory")

__device__ __forceinline__ void ldmA(uint32_t a[4], uint32_t su, int rowbase, int kbase, int lane) {
    int grp = lane >> 3, ri = lane & 7;
    int row = rowbase + ri + ((grp & 1) << 3);
    int col = kbase + ((grp & 2) << 2);
    uint32_t addr = su + (uint32_t)(row * ROWB + col * 2);
    asm volatile("ldmatrix.sync.aligned.m8n8.x4.shared.b16 {%0,%1,%2,%3}, [%4];"
                 : "=r"(a[0]), "=r"(a[1]), "=r"(a[2]), "=r"(a[3]) : "r"(addr));
}
__device__ __forceinline__ void mma16816(float c[4], const uint32_t a[4], uint32_t b0, uint32_t b1) {
    asm volatile(
        "mma.sync.aligned.m16n8k16.row.col.f32.bf16.bf16.f32 "
        "{%0,%1,%2,%3},{%4,%5,%6,%7},{%8,%9},{%0,%1,%2,%3};"
        : "+f"(c[0]), "+f"(c[1]), "+f"(c[2]), "+f"(c[3])
        : "r"(a[0]), "r"(a[1]), "r"(a[2]), "r"(a[3]), "r"(b0), "r"(b1));
}
// pack two f32 -> bf16x2 (lo in low half), and residual helpers
__device__ __forceinline__ uint32_t cvt_bf16x2(float lo, float hi) {
    uint32_t d;
    asm("cvt.rn.bf16x2.f32 %0, %1, %2;" : "=r"(d) : "f"(hi), "f"(lo));
    return d;
}

// ---------------------------------------------------------------------------
// feature build (one point per thread)
// ---------------------------------------------------------------------------
__device__ __forceinline__ void put_feat(__nv_bfloat16* aH, __nv_bfloat16* aL, int col, float v) {
    __nv_bfloat16 h = __float2bfloat16_rn(v);
    aH[col] = h;
    aL[col] = __float2bfloat16_rn(v - __bfloat162float(h));
}
__device__ void build_feat(char* actH, char* actL, int row, int bp,
                           const float* __restrict__ pts, const float* __restrict__ latent) {
    __nv_bfloat16* aH = (__nv_bfloat16*)(actH + row * ROWB);
    __nv_bfloat16* aL = (__nv_bfloat16*)(actL + row * ROWB);
    float px = pts[bp * 3 + 0], py = pts[bp * 3 + 1], pz = pts[bp * 3 + 2];
    float gx = g_gshift[bp * 3 + 0], gy = g_gshift[bp * 3 + 1], gz = g_gshift[bp * 3 + 2];
    put_feat(aH, aL, 0, px); put_feat(aH, aL, 1, py); put_feat(aH, aL, 2, pz);
#pragma unroll
    for (int l = 0; l < 10; ++l) {
        float f = (float)(1 << l);
        float s, c;
        __sincosf(px * f, &s, &c); put_feat(aH, aL, 3 + 6 * l + 0, s); put_feat(aH, aL, 3 + 6 * l + 3, c);
        __sincosf(py * f, &s, &c); put_feat(aH, aL, 3 + 6 * l + 1, s); put_feat(aH, aL, 3 + 6 * l + 4, c);
        __sincosf(pz * f, &s, &c); put_feat(aH, aL, 3 + 6 * l + 2, s); put_feat(aH, aL, 3 + 6 * l + 5, c);
    }
    put_feat(aH, aL, 63, gx); put_feat(aH, aL, 64, gy); put_feat(aH, aL, 65, gz);
#pragma unroll
    for (int l = 0; l < 2; ++l) {
        float f = (float)(1 << l);
        float s, c;
        __sincosf(gx * f, &s, &c); put_feat(aH, aL, 66 + 6 * l + 0, s); put_feat(aH, aL, 66 + 6 * l + 3, c);
        __sincosf(gy * f, &s, &c); put_feat(aH, aL, 66 + 6 * l + 1, s); put_feat(aH, aL, 66 + 6 * l + 4, c);
        __sincosf(gz * f, &s, &c); put_feat(aH, aL, 66 + 6 * l + 2, s); put_feat(aH, aL, 66 + 6 * l + 5, c);
    }
#pragma unroll
    for (int j = 0; j < 32; ++j) put_feat(aH, aL, 78 + j, latent[(size_t)bp * LAT + j]);
    __nv_bfloat16 z = __float2bfloat16_rn(0.f);
#pragma unroll
    for (int j = 110; j < 128; ++j) { aH[j] = z; aL[j] = z; }
}

// ---------------------------------------------------------------------------
// SMEM layout (256-thread CTA, 256 points)
// ---------------------------------------------------------------------------
#define OFF_AH   0
#define OFF_AL   69632
#define OFF_W    139264
#define OFF_BIAS 204800
#define OFF_WOUT 208896
#define OFF_BOUT 210432
#define SMEM_MLP 210448

__global__ void __launch_bounds__(256, 1)
mlp_mma_kernel(const float* __restrict__ pts, const float* __restrict__ latent,
               const float* __restrict__ b0, const float* __restrict__ b1,
               const float* __restrict__ b2, const float* __restrict__ b3,
               const float* __restrict__ b4, const float* __restrict__ b5,
               const float* __restrict__ b6, const float* __restrict__ b7,
               const float* __restrict__ w_out, const float* __restrict__ b_out,
               float* __restrict__ out) {
    extern __shared__ char sm[];
    char* actH = sm + OFF_AH;
    char* actL = sm + OFF_AL;
    float* sbias = (float*)(sm + OFF_BIAS);
    float* swout = (float*)(sm + OFF_WOUT);
    float* sbout = (float*)(sm + OFF_BOUT);

    const int tid = threadIdx.x;
    const int wid = tid >> 5;
    const int lane = tid & 31;
    const int bp0 = blockIdx.x * 256;
    const int bp = bp0 + tid;
    const uint32_t suH = smem_u32(actH);
    const uint32_t suL = smem_u32(actL);
    const uint32_t suW = smem_u32(sm + OFF_W);
    const int mrow = wid * 32;

    // stage biases / head weights
    {
        const float* bs[8] = {b0, b1, b2, b3, b4, b5, b6, b7};
        for (int i = tid; i < 1024; i += 256) sbias[i] = bs[i >> 7][i & 127];
        for (int i = tid; i < 384; i += 256) swout[i] = w_out[i];
        if (tid < 3) sbout[tid] = b_out[tid];
    }

    build_feat(actH, actL, tid, bp, pts, latent);
    __syncthreads();

    float c[2][16][4];

    // step tables: s index into g_wfrag, zero acc?, epilogue layer (-1 none), rebuild init?
    const int stepS[NSUB]    = {0, 1, 2, 3, 5, 4, 6, 7, 8};
    const int stepZero[NSUB] = {1, 1, 1, 1, 1, 0, 1, 1, 1};
    const int stepEpi[NSUB]  = {0, 1, 2, 3, -1, 4, 5, 6, 7};
    const int stepReb[NSUB]  = {0, 0, 0, 0, 0, 1, 0, 0, 0};

#pragma unroll 1
    for (int st = 0; st < NSUB; ++st) {
        const int s = stepS[st];

        // ---- stage Whi+Wlo (64KB) via cp.async ----
        __syncthreads();
        {
            const char* src = (const char*)(g_wfrag + (size_t)s * 4096);
#pragma unroll
            for (int i = 0; i < 16; ++i) {
                uint32_t off = (uint32_t)(tid + 256 * i) * 16u;
                CP_ASYNC16(suW + off, src + off);
            }
            CP_COMMIT();
            CP_WAIT0();
        }
        __syncthreads();

        if (stepZero[st]) {
#pragma unroll
            for (int mt = 0; mt < 2; ++mt)
#pragma unroll
                for (int nt = 0; nt < 16; ++nt)
#pragma unroll
                    for (int j = 0; j < 4; ++j) c[mt][nt][j] = 0.f;
        }
        if (stepReb[st]) {
            build_feat(actH, actL, tid, bp, pts, latent);
            __syncwarp();
        }

        // ---- fused MMA: per ks, A once, 12 MMAs per nt-pair ----
#pragma unroll 1
        for (int ks = 0; ks < 8; ++ks) {
            uint32_t ah0[4], ah1[4], al0[4], al1[4];
            ldmA(ah0, suH, mrow, ks * 16, lane);
            ldmA(ah1, suH, mrow + 16, ks * 16, lane);
            ldmA(al0, suL, mrow, ks * 16, lane);
            ldmA(al1, suL, mrow + 16, ks * 16, lane);
#pragma unroll
            for (int np = 0; np < 8; ++np) {
                uint32_t boff = ((uint32_t)(ks * 8 + np) * 32 + lane) * 16u;
                uint4 BH = *reinterpret_cast<const uint4*>(sm + OFF_W + boff);
                uint4 BL = *reinterpret_cast<const uint4*>(sm + OFF_W + 32768 + boff);
                // nt = 2np
                mma16816(c[0][2 * np], ah0, BH.x, BH.y);
                mma16816(c[1][2 * np], ah1, BH.x, BH.y);
                mma16816(c[0][2 * np], al0, BH.x, BH.y);
                mma16816(c[1][2 * np], al1, BH.x, BH.y);
                mma16816(c[0][2 * np], ah0, BL.x, BL.y);
                mma16816(c[1][2 * np], ah1, BL.x, BL.y);
                // nt = 2np+1
                mma16816(c[0][2 * np + 1], ah0, BH.z, BH.w);
                mma16816(c[1][2 * np + 1], ah1, BH.z, BH.w);
                mma16816(c[0][2 * np + 1], al0, BH.z, BH.w);
                mma16816(c[1][2 * np + 1], al1, BH.z, BH.w);
                mma16816(c[0][2 * np + 1], ah0, BL.z, BL.w);
                mma16816(c[1][2 * np + 1], ah1, BL.z, BL.w);
            }
        }

        const int l = stepEpi[st];
        if (l < 0) continue;
        __syncwarp();

        if (l < 7) {
            const float* bia = sbias + l * 128;
#pragma unroll
            for (int nt = 0; nt < 16; ++nt) {
                const int n0 = nt * 8 + (lane & 3) * 2;
                float2 bb = *reinterpret_cast<const float2*>(bia + n0);
#pragma unroll
                for (int mt = 0; mt < 2; ++mt) {
                    const int r0 = mrow + mt * 16 + (lane >> 2);
                    float v0 = fmaxf(c[mt][nt][0] + bb.x, 0.f);
                    float v1 = fmaxf(c[mt][nt][1] + bb.y, 0.f);
                    float v2 = fmaxf(c[mt][nt][2] + bb.x, 0.f);
                    float v3 = fmaxf(c[mt][nt][3] + bb.y, 0.f);
                    uint32_t h01 = cvt_bf16x2(v0, v1);
                    uint32_t h23 = cvt_bf16x2(v2, v3);
                    float l0 = v0 - __uint_as_float(h01 << 16);
                    float l1 = v1 - __uint_as_float(h01 & 0xFFFF0000u);
                    float l2 = v2 - __uint_as_float(h23 << 16);
                    float l3 = v3 - __uint_as_float(h23 & 0xFFFF0000u);
                    uint32_t q01 = cvt_bf16x2(l0, l1);
                    uint32_t q23 = cvt_bf16x2(l2, l3);
                    *(uint32_t*)(actH + r0 * ROWB + n0 * 2) = h01;
                    *(uint32_t*)(actH + (r0 + 8) * ROWB + n0 * 2) = h23;
                    *(uint32_t*)(actL + r0 * ROWB + n0 * 2) = q01;
                    *(uint32_t*)(actL + (r0 + 8) * ROWB + n0 * 2) = q23;
                }
            }
            __syncwarp();
        } else {
            // final layer: write pre-activation last_feat, compute output head
            const float* bia = sbias + 7 * 128;
            float* out2 = out + (size_t)NPTS * 3;
            float hs[2][2][3];
#pragma unroll
            for (int mt = 0; mt < 2; ++mt)
#pragma unroll
                for (int rr = 0; rr < 2; ++rr)
#pragma unroll
                    for (int cc = 0; cc < 3; ++cc) hs[mt][rr][cc] = 0.f;
#pragma unroll
            for (int nt = 0; nt < 16; ++nt) {
                const int n0 = nt * 8 + (lane & 3) * 2;
                float2 bb = *reinterpret_cast<const float2*>(bia + n0);
#pragma unroll
                for (int mt = 0; mt < 2; ++mt) {
                    const int r0 = mrow + mt * 16 + (lane >> 2);
                    float pre0 = c[mt][nt][0] + bb.x;
                    float pre1 = c[mt][nt][1] + bb.y;
                    float pre2 = c[mt][nt][2] + bb.x;
                    float pre3 = c[mt][nt][3] + bb.y;
                    *(float2*)(out2 + (size_t)(bp0 + r0) * HID + n0) = make_float2(pre0, pre1);
                    *(float2*)(out2 + (size_t)(bp0 + r0 + 8) * HID + n0) = make_float2(pre2, pre3);
                    float a0 = fmaxf(pre0, 0.f), a1 = fmaxf(pre1, 0.f);
                    float a2 = fmaxf(pre2, 0.f), a3 = fmaxf(pre3, 0.f);
#pragma unroll
                    for (int cc = 0; cc < 3; ++cc) {
                        hs[mt][0][cc] = fmaf(a0, swout[cc * 128 + n0], hs[mt][0][cc]);
                        hs[mt][0][cc] = fmaf(a1, swout[cc * 128 + n0 + 1], hs[mt][0][cc]);
                        hs[mt][1][cc] = fmaf(a2, swout[cc * 128 + n0], hs[mt][1][cc]);
                        hs[mt][1][cc] = fmaf(a3, swout[cc * 128 + n0 + 1], hs[mt][1][cc]);
                    }
                }
            }
#pragma unroll
            for (int mt = 0; mt < 2; ++mt)
#pragma unroll
                for (int rr = 0; rr < 2; ++rr)
#pragma unroll
                    for (int cc = 0; cc < 3; ++cc) {
                        float v = hs[mt][rr][cc];
                        v += __shfl_xor_sync(0xffffffffu, v, 1);
                        v += __shfl_xor_sync(0xffffffffu, v, 2);
                        hs[mt][rr][cc] = v;
                    }
            if ((lane & 3) == 0) {
#pragma unroll
                for (int mt = 0; mt < 2; ++mt)
#pragma unroll
                    for (int rr = 0; rr < 2; ++rr) {
                        const int r = mrow + mt * 16 + (lane >> 2) + rr * 8;
                        const int gp = bp0 + r;
#pragma unroll
                        for (int cc = 0; cc < 3; ++cc)
                            out[gp * 3 + cc] = pts[gp * 3 + cc] + g_gshift[gp * 3 + cc]
                                               + hs[mt][rr][cc] + sbout[cc];
                    }
            }
        }
    }
}

// ---------------------------------------------------------------------------
extern "C" void kernel_launch(void* const* d_in, const int* in_sizes, int n_in,
                              void* d_out, int out_size) {
    const float* pts      = (const float*)d_in[0];
    const float* deformed = (const float*)d_in[1];
    const float* cano     = (const float*)d_in[2];
    const float* latent   = (const float*)d_in[3];
    const float* w[8];
    const float* b[8];
    for (int i = 0; i < 8; ++i) {
        w[i] = (const float*)d_in[4 + 2 * i];
        b[i] = (const float*)d_in[5 + 2 * i];
    }
    const float* w_out = (const float*)d_in[20];
    const float* b_out = (const float*)d_in[21];
    float* out = (float*)d_out;

    const int smem_nn = VV * 16;
    cudaFuncSetAttribute(nn_kernel, cudaFuncAttributeMaxDynamicSharedMemorySize, smem_nn);
    cudaFuncSetAttribute(mlp_mma_kernel, cudaFuncAttributeMaxDynamicSharedMemorySize, SMEM_MLP);

    prep_wfrag<<<144, 256>>>(w[0], w[1], w[2], w[3], w[4], w[5], w[6], w[7]);
    nn_kernel<<<NPTS / 512, 256, smem_nn>>>(pts, deformed, cano);
    mlp_mma_kernel<<<NPTS / 256, 256, SMEM_MLP>>>(pts, latent, b[0], b[1], b[2], b[3], b[4],
                                                  b[5], b[6], b[7], w_out, b_out, out);
}

// round 12
// speedup vs baseline: 1.2508x; 1.2508x over previous
#include <cuda_runtime.h>
#include <cuda_fp16.h>
#include <cstdint>

#define BB 2
#define PP 32768
#define VV 5023
#define LAT 32
#define HID 128
#define NPTS (BB*PP)
#define NSUB 9
#define ROWB 272          // bytes per activation row (128 fp16 + 16B pad -> conflict-free ldmatrix)

// Weight fragments (fp16 hi/lo), uint4-paired: [s][h][ks][np][lane]
__device__ uint4 g_wfrag[NSUB * 2 * 8 * 8 * 32];
__device__ float g_gshift[NPTS * 3];

// ---------------------------------------------------------------------------
__global__ void prep_wfrag(const float* w0, const float* w1, const float* w2,
                           const float* w3, const float* w4, const float* w5,
                           const float* w6, const float* w7) {
    int idx = blockIdx.x * blockDim.x + threadIdx.x;
    if (idx >= NSUB * 2 * 8 * 8 * 32) return;
    int lane = idx & 31;
    int np = (idx >> 5) & 7;
    int ks = (idx >> 8) & 7;
    int h  = (idx >> 11) & 1;
    int s  = idx >> 12;

    const float* w; int Ktot, k0, valid;
    switch (s) {
        case 0: w = w0; Ktot = 110; k0 = 0;   valid = 110; break;
        case 1: w = w1; Ktot = 128; k0 = 0;   valid = 128; break;
        case 2: w = w2; Ktot = 128; k0 = 0;   valid = 128; break;
        case 3: w = w3; Ktot = 128; k0 = 0;   valid = 128; break;
        case 4: w = w4; Ktot = 238; k0 = 0;   valid = 110; break;   // l4 init part
        case 5: w = w4; Ktot = 238; k0 = 110; valid = 128; break;   // l4 hidden part
        case 6: w = w5; Ktot = 128; k0 = 0;   valid = 128; break;
        case 7: w = w6; Ktot = 128; k0 = 0;   valid = 128; break;
        default: w = w7; Ktot = 128; k0 = 0;  valid = 128; break;
    }
    uint32_t frag[2][2];
#pragma unroll
    for (int d = 0; d < 2; ++d) {
        int nt = 2 * np + d;
        int n = nt * 8 + (lane >> 2);
        int kb = ks * 16 + (lane & 3) * 2;
        unsigned short v16[4];
#pragma unroll
        for (int j = 0; j < 4; ++j) {
            int kk = kb + (j & 1) + (j >> 1) * 8;
            float v = (kk < valid) ? w[n * Ktot + k0 + kk] : 0.f;
            __half hi = __float2half_rn(v);
            __half r = (h == 0) ? hi : __float2half_rn(v - __half2float(hi));
            v16[j] = __half_as_ushort(r);
        }
        frag[d][0] = (uint32_t)v16[0] | ((uint32_t)v16[1] << 16);
        frag[d][1] = (uint32_t)v16[2] | ((uint32_t)v16[3] << 16);
    }
    g_wfrag[idx] = make_uint4(frag[0][0], frag[0][1], frag[1][0], frag[1][1]);
}

// ---------------------------------------------------------------------------
// NN search + gshift (unchanged)
// ---------------------------------------------------------------------------
__global__ void nn_kernel(const float* __restrict__ pts,
                          const float* __restrict__ deformed,
                          const float* __restrict__ cano) {
    extern __shared__ float4 sv[];
    const int blockBase = blockIdx.x * 512;
    const int b = blockBase / PP;
    const float* dv = deformed + (size_t)b * VV * 3;
    for (int v = threadIdx.x; v < VV; v += 256) {
        float x = dv[3 * v + 0], y = dv[3 * v + 1], z = dv[3 * v + 2];
        sv[v] = make_float4(x, y, z, 0.5f * (x * x + y * y + z * z));
    }
    __syncthreads();
    const int pA = blockBase + threadIdx.x;
    const int pB = pA + 256;
    float ax = pts[pA * 3 + 0], ay = pts[pA * 3 + 1], az = pts[pA * 3 + 2];
    float bx = pts[pB * 3 + 0], by = pts[pB * 3 + 1], bz = pts[pB * 3 + 2];
    float bsA = 3.4e38f, bsB = 3.4e38f;
    int iA = 0, iB = 0;
#pragma unroll 4
    for (int v = 0; v < VV; ++v) {
        float4 q = sv[v];
        float sA = fmaf(-q.x, ax, fmaf(-q.y, ay, fmaf(-q.z, az, q.w)));
        float sB = fmaf(-q.x, bx, fmaf(-q.y, by, fmaf(-q.z, bz, q.w)));
        if (sA < bsA) { bsA = sA; iA = v; }
        if (sB < bsB) { bsB = sB; iB = v; }
    }
    {
        float p2 = fmaf(ax, ax, fmaf(ay, ay, az * az));
        float w = __expf(-fmaxf(fmaf(2.f, bsA, p2), 0.f));
        float4 q = sv[iA];
        g_gshift[pA * 3 + 0] = (cano[iA * 3 + 0] - q.x) * w;
        g_gshift[pA * 3 + 1] = (cano[iA * 3 + 1] - q.y) * w;
        g_gshift[pA * 3 + 2] = (cano[iA * 3 + 2] - q.z) * w;
    }
    {
        float p2 = fmaf(bx, bx, fmaf(by, by, bz * bz));
        float w = __expf(-fmaxf(fmaf(2.f, bsB, p2), 0.f));
        float4 q = sv[iB];
        g_gshift[pB * 3 + 0] = (cano[iB * 3 + 0] - q.x) * w;
        g_gshift[pB * 3 + 1] = (cano[iB * 3 + 1] - q.y) * w;
        g_gshift[pB * 3 + 2] = (cano[iB * 3 + 2] - q.z) * w;
    }
}

// ---------------------------------------------------------------------------
// helpers
// ---------------------------------------------------------------------------
__device__ __forceinline__ uint32_t smem_u32(const void* p) {
    uint32_t a;
    asm("{ .reg .u64 t; cvta.to.shared.u64 t, %1; cvt.u32.u64 %0, t; }" : "=r"(a) : "l"(p));
    return a;
}
#define CP_ASYNC16(dst, src) \
    asm volatile("cp.async.cg.shared.global [%0], [%1], 16;" :: "r"(dst), "l"(src))
#define CP_COMMIT() asm volatile("cp.async.commit_group;" ::: "memory")
#define CP_WAIT1()  asm volatile("cp.async.wait_group 1;" ::: "memory")

__device__ __forceinline__ void ldmA(uint32_t a[4], uint32_t su, int rowbase, int kbase, int lane) {
    int grp = lane >> 3, ri = lane & 7;
    int row = rowbase + ri + ((grp & 1) << 3);
    int col = kbase + ((grp & 2) << 2);
    uint32_t addr = su + (uint32_t)(row * ROWB + col * 2);
    asm volatile("ldmatrix.sync.aligned.m8n8.x4.shared.b16 {%0,%1,%2,%3}, [%4];"
                 : "=r"(a[0]), "=r"(a[1]), "=r"(a[2]), "=r"(a[3]) : "r"(addr));
}
__device__ __forceinline__ void mma16816(float c[4], const uint32_t a[4], uint32_t b0, uint32_t b1) {
    asm volatile(
        "mma.sync.aligned.m16n8k16.row.col.f32.f16.f16.f32 "
        "{%0,%1,%2,%3},{%4,%5,%6,%7},{%8,%9},{%0,%1,%2,%3};"
        : "+f"(c[0]), "+f"(c[1]), "+f"(c[2]), "+f"(c[3])
        : "r"(a[0]), "r"(a[1]), "r"(a[2]), "r"(a[3]), "r"(b0), "r"(b1));
}
__device__ __forceinline__ uint32_t pack_h2(float lo, float hi) {
    __half2 h = __floats2half2_rn(lo, hi);
    return *reinterpret_cast<uint32_t*>(&h);
}

// ---------------------------------------------------------------------------
// feature build (one point per thread) -> single fp16 buffer
// ---------------------------------------------------------------------------
__device__ void build_feat(char* act, int row, int bp,
                           const float* __restrict__ pts, const float* __restrict__ latent) {
    __half* a = (__half*)(act + row * ROWB);
    float px = pts[bp * 3 + 0], py = pts[bp * 3 + 1], pz = pts[bp * 3 + 2];
    float gx = g_gshift[bp * 3 + 0], gy = g_gshift[bp * 3 + 1], gz = g_gshift[bp * 3 + 2];
    a[0] = __float2half_rn(px); a[1] = __float2half_rn(py); a[2] = __float2half_rn(pz);
#pragma unroll
    for (int l = 0; l < 10; ++l) {
        float f = (float)(1 << l);
        float s, c;
        __sincosf(px * f, &s, &c); a[3 + 6 * l + 0] = __float2half_rn(s); a[3 + 6 * l + 3] = __float2half_rn(c);
        __sincosf(py * f, &s, &c); a[3 + 6 * l + 1] = __float2half_rn(s); a[3 + 6 * l + 4] = __float2half_rn(c);
        __sincosf(pz * f, &s, &c); a[3 + 6 * l + 2] = __float2half_rn(s); a[3 + 6 * l + 5] = __float2half_rn(c);
    }
    a[63] = __float2half_rn(gx); a[64] = __float2half_rn(gy); a[65] = __float2half_rn(gz);
#pragma unroll
    for (int l = 0; l < 2; ++l) {
        float f = (float)(1 << l);
        float s, c;
        __sincosf(gx * f, &s, &c); a[66 + 6 * l + 0] = __float2half_rn(s); a[66 + 6 * l + 3] = __float2half_rn(c);
        __sincosf(gy * f, &s, &c); a[66 + 6 * l + 1] = __float2half_rn(s); a[66 + 6 * l + 4] = __float2half_rn(c);
        __sincosf(gz * f, &s, &c); a[66 + 6 * l + 2] = __float2half_rn(s); a[66 + 6 * l + 5] = __float2half_rn(c);
    }
#pragma unroll
    for (int j = 0; j < 32; ++j) a[78 + j] = __float2half_rn(latent[(size_t)bp * LAT + j]);
    __half z = __float2half_rn(0.f);
#pragma unroll
    for (int j = 110; j < 128; ++j) a[j] = z;
}

// ---------------------------------------------------------------------------
// SMEM layout (128-thread CTA, 128 points) -> 2 CTAs/SM
// ---------------------------------------------------------------------------
#define OFF_A    0
#define OFF_WH   34816
#define OFF_WL   67584
#define OFF_BIAS 100352
#define OFF_WOUT 104448
#define OFF_BOUT 105984
#define SMEM_MLP 106000

__global__ void __launch_bounds__(128, 2)
mlp_mma_kernel(const float* __restrict__ pts, const float* __restrict__ latent,
               const float* __restrict__ b0, const float* __restrict__ b1,
               const float* __restrict__ b2, const float* __restrict__ b3,
               const float* __restrict__ b4, const float* __restrict__ b5,
               const float* __restrict__ b6, const float* __restrict__ b7,
               const float* __restrict__ w_out, const float* __restrict__ b_out,
               float* __restrict__ out) {
    extern __shared__ char sm[];
    char* act = sm + OFF_A;
    float* sbias = (float*)(sm + OFF_BIAS);
    float* swout = (float*)(sm + OFF_WOUT);
    float* sbout = (float*)(sm + OFF_BOUT);

    const int tid = threadIdx.x;
    const int wid = tid >> 5;
    const int lane = tid & 31;
    const int bp0 = blockIdx.x * 128;
    const int bp = bp0 + tid;
    const uint32_t suA = smem_u32(act);
    const uint32_t suWH = smem_u32(sm + OFF_WH);
    const uint32_t suWL = smem_u32(sm + OFF_WL);
    const int mrow = wid * 32;

    // step tables
    const int stepS[NSUB]    = {0, 1, 2, 3, 5, 4, 6, 7, 8};
    const int stepZero[NSUB] = {1, 1, 1, 1, 1, 0, 1, 1, 1};
    const int stepEpi[NSUB]  = {0, 1, 2, 3, -1, 4, 5, 6, 7};
    const int stepReb[NSUB]  = {0, 0, 0, 0, 0, 1, 0, 0, 0};

    // prologue: start loading BH0 and BL0 (32KB each, 64 x 16B per thread each)
    {
        const char* src = (const char*)(g_wfrag + (size_t)stepS[0] * 4096);
#pragma unroll
        for (int i = 0; i < 16; ++i) {
            uint32_t off = (uint32_t)(tid + 128 * i) * 16u;
            CP_ASYNC16(suWH + off, src + off);
        }
        CP_COMMIT();
#pragma unroll
        for (int i = 0; i < 16; ++i) {
            uint32_t off = (uint32_t)(tid + 128 * i) * 16u;
            CP_ASYNC16(suWL + off, src + 32768 + off);
        }
        CP_COMMIT();
    }

    // stage biases / head weights
    {
        const float* bs[8] = {b0, b1, b2, b3, b4, b5, b6, b7};
        for (int i = tid; i < 1024; i += 128) sbias[i] = bs[i >> 7][i & 127];
        for (int i = tid; i < 384; i += 128) swout[i] = w_out[i];
        if (tid < 3) sbout[tid] = b_out[tid];
    }

    build_feat(act, tid, bp, pts, latent);
    __syncthreads();

    float c[2][16][4];

#pragma unroll 1
    for (int st = 0; st < NSUB; ++st) {
        if (stepZero[st]) {
#pragma unroll
            for (int mt = 0; mt < 2; ++mt)
#pragma unroll
                for (int nt = 0; nt < 16; ++nt)
#pragma unroll
                    for (int j = 0; j < 4; ++j) c[mt][nt][j] = 0.f;
        }
        if (stepReb[st]) {
            build_feat(act, tid, bp, pts, latent);
            __syncwarp();
        }

        // ---- phase 1: BH products (wait: allow 1 pending = BL_st) ----
        CP_WAIT1();
        __syncthreads();
#pragma unroll 1
        for (int ks = 0; ks < 8; ++ks) {
            uint32_t a0[4], a1[4];
            ldmA(a0, suA, mrow, ks * 16, lane);
            ldmA(a1, suA, mrow + 16, ks * 16, lane);
#pragma unroll
            for (int np = 0; np < 8; ++np) {
                uint32_t boff = ((uint32_t)(ks * 8 + np) * 32 + lane) * 16u;
                uint4 B = *reinterpret_cast<const uint4*>(sm + OFF_WH + boff);
                mma16816(c[0][2 * np], a0, B.x, B.y);
                mma16816(c[1][2 * np], a1, B.x, B.y);
                mma16816(c[0][2 * np + 1], a0, B.z, B.w);
                mma16816(c[1][2 * np + 1], a1, B.z, B.w);
            }
        }
        __syncthreads();
        if (st + 1 < NSUB) {  // prefetch BH_{st+1}
            const char* src = (const char*)(g_wfrag + (size_t)stepS[st + 1] * 4096);
#pragma unroll
            for (int i = 0; i < 16; ++i) {
                uint32_t off = (uint32_t)(tid + 128 * i) * 16u;
                CP_ASYNC16(suWH + off, src + off);
            }
            CP_COMMIT();
        }

        // ---- phase 2: BL products (wait: allow 1 pending = BH_{st+1}) ----
        CP_WAIT1();
        __syncthreads();
#pragma unroll 1
        for (int ks = 0; ks < 8; ++ks) {
            uint32_t a0[4], a1[4];
            ldmA(a0, suA, mrow, ks * 16, lane);
            ldmA(a1, suA, mrow + 16, ks * 16, lane);
#pragma unroll
            for (int np = 0; np < 8; ++np) {
                uint32_t boff = ((uint32_t)(ks * 8 + np) * 32 + lane) * 16u;
                uint4 B = *reinterpret_cast<const uint4*>(sm + OFF_WL + boff);
                mma16816(c[0][2 * np], a0, B.x, B.y);
                mma16816(c[1][2 * np], a1, B.x, B.y);
                mma16816(c[0][2 * np + 1], a0, B.z, B.w);
                mma16816(c[1][2 * np + 1], a1, B.z, B.w);
            }
        }
        __syncthreads();
        if (st + 1 < NSUB) {  // prefetch BL_{st+1}
            const char* src = (const char*)(g_wfrag + (size_t)stepS[st + 1] * 4096);
#pragma unroll
            for (int i = 0; i < 16; ++i) {
                uint32_t off = (uint32_t)(tid + 128 * i) * 16u;
                CP_ASYNC16(suWL + off, src + 32768 + off);
            }
            CP_COMMIT();
        }

        const int l = stepEpi[st];
        if (l < 0) continue;
        __syncwarp();

        if (l < 7) {
            const float* bia = sbias + l * 128;
#pragma unroll
            for (int nt = 0; nt < 16; ++nt) {
                const int n0 = nt * 8 + (lane & 3) * 2;
                float2 bb = *reinterpret_cast<const float2*>(bia + n0);
#pragma unroll
                for (int mt = 0; mt < 2; ++mt) {
                    const int r0 = mrow + mt * 16 + (lane >> 2);
                    float v0 = fmaxf(c[mt][nt][0] + bb.x, 0.f);
                    float v1 = fmaxf(c[mt][nt][1] + bb.y, 0.f);
                    float v2 = fmaxf(c[mt][nt][2] + bb.x, 0.f);
                    float v3 = fmaxf(c[mt][nt][3] + bb.y, 0.f);
                    *(uint32_t*)(act + r0 * ROWB + n0 * 2) = pack_h2(v0, v1);
                    *(uint32_t*)(act + (r0 + 8) * ROWB + n0 * 2) = pack_h2(v2, v3);
                }
            }
            __syncwarp();
        } else {
            // final layer: write pre-activation last_feat, compute output head
            const float* bia = sbias + 7 * 128;
            float* out2 = out + (size_t)NPTS * 3;
            float hs[2][2][3];
#pragma unroll
            for (int mt = 0; mt < 2; ++mt)
#pragma unroll
                for (int rr = 0; rr < 2; ++rr)
#pragma unroll
                    for (int cc = 0; cc < 3; ++cc) hs[mt][rr][cc] = 0.f;
#pragma unroll
            for (int nt = 0; nt < 16; ++nt) {
                const int n0 = nt * 8 + (lane & 3) * 2;
                float2 bb = *reinterpret_cast<const float2*>(bia + n0);
#pragma unroll
                for (int mt = 0; mt < 2; ++mt) {
                    const int r0 = mrow + mt * 16 + (lane >> 2);
                    float pre0 = c[mt][nt][0] + bb.x;
                    float pre1 = c[mt][nt][1] + bb.y;
                    float pre2 = c[mt][nt][2] + bb.x;
                    float pre3 = c[mt][nt][3] + bb.y;
                    *(float2*)(out2 + (size_t)(bp0 + r0) * HID + n0) = make_float2(pre0, pre1);
                    *(float2*)(out2 + (size_t)(bp0 + r0 + 8) * HID + n0) = make_float2(pre2, pre3);
                    float a0 = fmaxf(pre0, 0.f), a1 = fmaxf(pre1, 0.f);
                    float a2 = fmaxf(pre2, 0.f), a3 = fmaxf(pre3, 0.f);
#pragma unroll
                    for (int cc = 0; cc < 3; ++cc) {
                        hs[mt][0][cc] = fmaf(a0, swout[cc * 128 + n0], hs[mt][0][cc]);
                        hs[mt][0][cc] = fmaf(a1, swout[cc * 128 + n0 + 1], hs[mt][0][cc]);
                        hs[mt][1][cc] = fmaf(a2, swout[cc * 128 + n0], hs[mt][1][cc]);
                        hs[mt][1][cc] = fmaf(a3, swout[cc * 128 + n0 + 1], hs[mt][1][cc]);
                    }
                }
            }
#pragma unroll
            for (int mt = 0; mt < 2; ++mt)
#pragma unroll
                for (int rr = 0; rr < 2; ++rr)
#pragma unroll
                    for (int cc = 0; cc < 3; ++cc) {
                        float v = hs[mt][rr][cc];
                        v += __shfl_xor_sync(0xffffffffu, v, 1);
                        v += __shfl_xor_sync(0xffffffffu, v, 2);
                        hs[mt][rr][cc] = v;
                    }
            if ((lane & 3) == 0) {
#pragma unroll
                for (int mt = 0; mt < 2; ++mt)
#pragma unroll
                    for (int rr = 0; rr < 2; ++rr) {
                        const int r = mrow + mt * 16 + (lane >> 2) + rr * 8;
                        const int gp = bp0 + r;
#pragma unroll
                        for (int cc = 0; cc < 3; ++cc)
                            out[gp * 3 + cc] = pts[gp * 3 + cc] + g_gshift[gp * 3 + cc]
                                               + hs[mt][rr][cc] + sbout[cc];
                    }
            }
        }
    }
}

// ---------------------------------------------------------------------------
extern "C" void kernel_launch(void* const* d_in, const int* in_sizes, int n_in,
                              void* d_out, int out_size) {
    const float* pts      = (const float*)d_in[0];
    const float* deformed = (const float*)d_in[1];
    const float* cano     = (const float*)d_in[2];
    const float* latent   = (const float*)d_in[3];
    const float* w[8];
    const float* b[8];
    for (int i = 0; i < 8; ++i) {
        w[i] = (const float*)d_in[4 + 2 * i];
        b[i] = (const float*)d_in[5 + 2 * i];
    }
    const float* w_out = (const float*)d_in[20];
    const float* b_out = (const float*)d_in[21];
    float* out = (float*)d_out;

    const int smem_nn = VV * 16;
    cudaFuncSetAttribute(nn_kernel, cudaFuncAttributeMaxDynamicSharedMemorySize, smem_nn);
    cudaFuncSetAttribute(mlp_mma_kernel, cudaFuncAttributeMaxDynamicSharedMemorySize, SMEM_MLP);

    prep_wfrag<<<144, 256>>>(w[0], w[1], w[2], w[3], w[4], w[5], w[6], w[7]);
    nn_kernel<<<NPTS / 512, 256, smem_nn>>>(pts, deformed, cano);
    mlp_mma_kernel<<<NPTS / 128, 128, SMEM_MLP>>>(pts, latent, b[0], b[1], b[2], b[3], b[4],
                                                  b[5], b[6], b[7], w_out, b_out, out);
}

// round 14
// speedup vs baseline: 1.5178x; 1.2134x over previous
#include <cuda_runtime.h>
#include <cuda_fp16.h>
#include <cstdint>

#define BB 2
#define PP 32768
#define VV 5023
#define LAT 32
#define HID 128
#define NPTS (BB*PP)
#define NSUB 9
#define ROWB 272          // bytes per activation row (128 fp16 + 16B pad -> conflict-free ldmatrix)

// Weight fragments (fp16, single product), uint4-paired: [s][ks][np][lane]
__device__ uint4 g_wfrag[NSUB * 8 * 8 * 32];
__device__ float g_gshift[NPTS * 3];

// ---------------------------------------------------------------------------
__global__ void prep_wfrag(const float* w0, const float* w1, const float* w2,
                           const float* w3, const float* w4, const float* w5,
                           const float* w6, const float* w7) {
    int idx = blockIdx.x * blockDim.x + threadIdx.x;
    if (idx >= NSUB * 8 * 8 * 32) return;
    int lane = idx & 31;
    int np = (idx >> 5) & 7;
    int ks = (idx >> 8) & 7;
    int s  = idx >> 11;

    const float* w; int Ktot, k0, valid;
    switch (s) {
        case 0: w = w0; Ktot = 110; k0 = 0;   valid = 110; break;
        case 1: w = w1; Ktot = 128; k0 = 0;   valid = 128; break;
        case 2: w = w2; Ktot = 128; k0 = 0;   valid = 128; break;
        case 3: w = w3; Ktot = 128; k0 = 0;   valid = 128; break;
        case 4: w = w4; Ktot = 238; k0 = 0;   valid = 110; break;   // l4 init part
        case 5: w = w4; Ktot = 238; k0 = 110; valid = 128; break;   // l4 hidden part
        case 6: w = w5; Ktot = 128; k0 = 0;   valid = 128; break;
        case 7: w = w6; Ktot = 128; k0 = 0;   valid = 128; break;
        default: w = w7; Ktot = 128; k0 = 0;  valid = 128; break;
    }
    uint32_t frag[2][2];
#pragma unroll
    for (int d = 0; d < 2; ++d) {
        int nt = 2 * np + d;
        int n = nt * 8 + (lane >> 2);
        int kb = ks * 16 + (lane & 3) * 2;
        unsigned short v16[4];
#pragma unroll
        for (int j = 0; j < 4; ++j) {
            int kk = kb + (j & 1) + (j >> 1) * 8;
            float v = (kk < valid) ? w[n * Ktot + k0 + kk] : 0.f;
            v16[j] = __half_as_ushort(__float2half_rn(v));
        }
        frag[d][0] = (uint32_t)v16[0] | ((uint32_t)v16[1] << 16);
        frag[d][1] = (uint32_t)v16[2] | ((uint32_t)v16[3] << 16);
    }
    g_wfrag[idx] = make_uint4(frag[0][0], frag[0][1], frag[1][0], frag[1][1]);
}

// ---------------------------------------------------------------------------
// NN search + gshift (unchanged)
// ---------------------------------------------------------------------------
__global__ void nn_kernel(const float* __restrict__ pts,
                          const float* __restrict__ deformed,
                          const float* __restrict__ cano) {
    extern __shared__ float4 sv[];
    const int blockBase = blockIdx.x * 512;
    const int b = blockBase / PP;
    const float* dv = deformed + (size_t)b * VV * 3;
    for (int v = threadIdx.x; v < VV; v += 256) {
        float x = dv[3 * v + 0], y = dv[3 * v + 1], z = dv[3 * v + 2];
        sv[v] = make_float4(x, y, z, 0.5f * (x * x + y * y + z * z));
    }
    __syncthreads();
    const int pA = blockBase + threadIdx.x;
    const int pB = pA + 256;
    float ax = pts[pA * 3 + 0], ay = pts[pA * 3 + 1], az = pts[pA * 3 + 2];
    float bx = pts[pB * 3 + 0], by = pts[pB * 3 + 1], bz = pts[pB * 3 + 2];
    float bsA = 3.4e38f, bsB = 3.4e38f;
    int iA = 0, iB = 0;
#pragma unroll 4
    for (int v = 0; v < VV; ++v) {
        float4 q = sv[v];
        float sA = fmaf(-q.x, ax, fmaf(-q.y, ay, fmaf(-q.z, az, q.w)));
        float sB = fmaf(-q.x, bx, fmaf(-q.y, by, fmaf(-q.z, bz, q.w)));
        if (sA < bsA) { bsA = sA; iA = v; }
        if (sB < bsB) { bsB = sB; iB = v; }
    }
    {
        float p2 = fmaf(ax, ax, fmaf(ay, ay, az * az));
        float w = __expf(-fmaxf(fmaf(2.f, bsA, p2), 0.f));
        float4 q = sv[iA];
        g_gshift[pA * 3 + 0] = (cano[iA * 3 + 0] - q.x) * w;
        g_gshift[pA * 3 + 1] = (cano[iA * 3 + 1] - q.y) * w;
        g_gshift[pA * 3 + 2] = (cano[iA * 3 + 2] - q.z) * w;
    }
    {
        float p2 = fmaf(bx, bx, fmaf(by, by, bz * bz));
        float w = __expf(-fmaxf(fmaf(2.f, bsB, p2), 0.f));
        float4 q = sv[iB];
        g_gshift[pB * 3 + 0] = (cano[iB * 3 + 0] - q.x) * w;
        g_gshift[pB * 3 + 1] = (cano[iB * 3 + 1] - q.y) * w;
        g_gshift[pB * 3 + 2] = (cano[iB * 3 + 2] - q.z) * w;
    }
}

// ---------------------------------------------------------------------------
// helpers
// ---------------------------------------------------------------------------
__device__ __forceinline__ uint32_t smem_u32(const void* p) {
    uint32_t a;
    asm("{ .reg .u64 t; cvta.to.shared.u64 t, %1; cvt.u32.u64 %0, t; }" : "=r"(a) : "l"(p));
    return a;
}
#define CP_ASYNC16(dst, src) \
    asm volatile("cp.async.cg.shared.global [%0], [%1], 16;" :: "r"(dst), "l"(src))
#define CP_COMMIT() asm volatile("cp.async.commit_group;" ::: "memory")
#define CP_WAIT1()  asm volatile("cp.async.wait_group 1;" ::: "memory")
#define CP_WAIT0()  asm volatile("cp.async.wait_group 0;" ::: "memory")

__device__ __forceinline__ void ldmA(uint32_t a[4], uint32_t su, int rowbase, int kbase, int lane) {
    int grp = lane >> 3, ri = lane & 7;
    int row = rowbase + ri + ((grp & 1) << 3);
    int col = kbase + ((grp & 2) << 2);
    uint32_t addr = su + (uint32_t)(row * ROWB + col * 2);
    asm volatile("ldmatrix.sync.aligned.m8n8.x4.shared.b16 {%0,%1,%2,%3}, [%4];"
                 : "=r"(a[0]), "=r"(a[1]), "=r"(a[2]), "=r"(a[3]) : "r"(addr));
}
__device__ __forceinline__ void mma16816(float c[4], const uint32_t a[4], uint32_t b0, uint32_t b1) {
    asm volatile(
        "mma.sync.aligned.m16n8k16.row.col.f32.f16.f16.f32 "
        "{%0,%1,%2,%3},{%4,%5,%6,%7},{%8,%9},{%0,%1,%2,%3};"
        : "+f"(c[0]), "+f"(c[1]), "+f"(c[2]), "+f"(c[3])
        : "r"(a[0]), "r"(a[1]), "r"(a[2]), "r"(a[3]), "r"(b0), "r"(b1));
}
__device__ __forceinline__ uint32_t pack_h2(float lo, float hi) {
    __half2 h = __floats2half2_rn(lo, hi);
    return *reinterpret_cast<uint32_t*>(&h);
}

// ---------------------------------------------------------------------------
// feature build (one point per thread) -> single fp16 buffer
// ---------------------------------------------------------------------------
__device__ void build_feat(char* act, int row, int bp,
                           const float* __restrict__ pts, const float* __restrict__ latent) {
    __half* a = (__half*)(act + row * ROWB);
    float px = pts[bp * 3 + 0], py = pts[bp * 3 + 1], pz = pts[bp * 3 + 2];
    float gx = g_gshift[bp * 3 + 0], gy = g_gshift[bp * 3 + 1], gz = g_gshift[bp * 3 + 2];
    a[0] = __float2half_rn(px); a[1] = __float2half_rn(py); a[2] = __float2half_rn(pz);
#pragma unroll
    for (int l = 0; l < 10; ++l) {
        float f = (float)(1 << l);
        float s, c;
        __sincosf(px * f, &s, &c); a[3 + 6 * l + 0] = __float2half_rn(s); a[3 + 6 * l + 3] = __float2half_rn(c);
        __sincosf(py * f, &s, &c); a[3 + 6 * l + 1] = __float2half_rn(s); a[3 + 6 * l + 4] = __float2half_rn(c);
        __sincosf(pz * f, &s, &c); a[3 + 6 * l + 2] = __float2half_rn(s); a[3 + 6 * l + 5] = __float2half_rn(c);
    }
    a[63] = __float2half_rn(gx); a[64] = __float2half_rn(gy); a[65] = __float2half_rn(gz);
#pragma unroll
    for (int l = 0; l < 2; ++l) {
        float f = (float)(1 << l);
        float s, c;
        __sincosf(gx * f, &s, &c); a[66 + 6 * l + 0] = __float2half_rn(s); a[66 + 6 * l + 3] = __float2half_rn(c);
        __sincosf(gy * f, &s, &c); a[66 + 6 * l + 1] = __float2half_rn(s); a[66 + 6 * l + 4] = __float2half_rn(c);
        __sincosf(gz * f, &s, &c); a[66 + 6 * l + 2] = __float2half_rn(s); a[66 + 6 * l + 5] = __float2half_rn(c);
    }
#pragma unroll
    for (int j = 0; j < 32; ++j) a[78 + j] = __float2half_rn(latent[(size_t)bp * LAT + j]);
    __half z = __float2half_rn(0.f);
#pragma unroll
    for (int j = 110; j < 128; ++j) a[j] = z;
}

// ---------------------------------------------------------------------------
// SMEM layout (128-thread CTA, 128 points) -> 2 CTAs/SM
// Double-buffered 32KB weight stages.
// ---------------------------------------------------------------------------
#define OFF_A    0
#define OFF_W0   34816
#define OFF_W1   67584
#define OFF_BIAS 100352
#define OFF_WOUT 104448
#define OFF_BOUT 105984
#define SMEM_MLP 106000

__global__ void __launch_bounds__(128, 2)
mlp_mma_kernel(const float* __restrict__ pts, const float* __restrict__ latent,
               const float* __restrict__ b0, const float* __restrict__ b1,
               const float* __restrict__ b2, const float* __restrict__ b3,
               const float* __restrict__ b4, const float* __restrict__ b5,
               const float* __restrict__ b6, const float* __restrict__ b7,
               const float* __restrict__ w_out, const float* __restrict__ b_out,
               float* __restrict__ out) {
    extern __shared__ char sm[];
    char* act = sm + OFF_A;
    float* sbias = (float*)(sm + OFF_BIAS);
    float* swout = (float*)(sm + OFF_WOUT);
    float* sbout = (float*)(sm + OFF_BOUT);

    const int tid = threadIdx.x;
    const int wid = tid >> 5;
    const int lane = tid & 31;
    const int bp0 = blockIdx.x * 128;
    const int bp = bp0 + tid;
    const uint32_t suA = smem_u32(act);
    const uint32_t suW[2] = {smem_u32(sm + OFF_W0), smem_u32(sm + OFF_W1)};
    const int mrow = wid * 32;

    // step tables
    const int stepS[NSUB]    = {0, 1, 2, 3, 5, 4, 6, 7, 8};
    const int stepZero[NSUB] = {1, 1, 1, 1, 1, 0, 1, 1, 1};
    const int stepEpi[NSUB]  = {0, 1, 2, 3, -1, 4, 5, 6, 7};
    const int stepReb[NSUB]  = {0, 0, 0, 0, 0, 1, 0, 0, 0};

    // prologue: prefetch L0 into buf0 (32KB = 2048 uint4, 16 per thread)
    {
        const char* src = (const char*)(g_wfrag + (size_t)stepS[0] * 2048);
#pragma unroll
        for (int i = 0; i < 16; ++i) {
            uint32_t off = (uint32_t)(tid + 128 * i) * 16u;
            CP_ASYNC16(suW[0] + off, src + off);
        }
        CP_COMMIT();
    }

    // stage biases / head weights
    {
        const float* bs[8] = {b0, b1, b2, b3, b4, b5, b6, b7};
        for (int i = tid; i < 1024; i += 128) sbias[i] = bs[i >> 7][i & 127];
        for (int i = tid; i < 384; i += 128) swout[i] = w_out[i];
        if (tid < 3) sbout[tid] = b_out[tid];
    }

    build_feat(act, tid, bp, pts, latent);

    float c[2][16][4];

#pragma unroll 1
    for (int st = 0; st < NSUB; ++st) {
        // prefetch next layer into the other buffer, then wait for this layer
        if (st + 1 < NSUB) {
            const char* src = (const char*)(g_wfrag + (size_t)stepS[st + 1] * 2048);
            uint32_t dst = suW[(st + 1) & 1];
#pragma unroll
            for (int i = 0; i < 16; ++i) {
                uint32_t off = (uint32_t)(tid + 128 * i) * 16u;
                CP_ASYNC16(dst + off, src + off);
            }
            CP_COMMIT();
            CP_WAIT1();
        } else {
            CP_WAIT0();
        }
        __syncthreads();

        if (stepZero[st]) {
#pragma unroll
            for (int mt = 0; mt < 2; ++mt)
#pragma unroll
                for (int nt = 0; nt < 16; ++nt)
#pragma unroll
                    for (int j = 0; j < 4; ++j) c[mt][nt][j] = 0.f;
        }
        if (stepReb[st]) {
            build_feat(act, tid, bp, pts, latent);
            __syncwarp();
        }

        const char* wbuf = sm + (((st & 1) == 0) ? OFF_W0 : OFF_W1);
#pragma unroll 1
        for (int ks = 0; ks < 8; ++ks) {
            uint32_t a0[4], a1[4];
            ldmA(a0, suA, mrow, ks * 16, lane);
            ldmA(a1, suA, mrow + 16, ks * 16, lane);
#pragma unroll
            for (int np = 0; np < 8; ++np) {
                uint32_t boff = ((uint32_t)(ks * 8 + np) * 32 + lane) * 16u;
                uint4 B = *reinterpret_cast<const uint4*>(wbuf + boff);
                mma16816(c[0][2 * np], a0, B.x, B.y);
                mma16816(c[1][2 * np], a1, B.x, B.y);
                mma16816(c[0][2 * np + 1], a0, B.z, B.w);
                mma16816(c[1][2 * np + 1], a1, B.z, B.w);
            }
        }

        const int l = stepEpi[st];
        if (l >= 0) {
            __syncwarp();
            if (l < 7) {
                const float* bia = sbias + l * 128;
#pragma unroll
                for (int nt = 0; nt < 16; ++nt) {
                    const int n0 = nt * 8 + (lane & 3) * 2;
                    float2 bb = *reinterpret_cast<const float2*>(bia + n0);
#pragma unroll
                    for (int mt = 0; mt < 2; ++mt) {
                        const int r0 = mrow + mt * 16 + (lane >> 2);
                        float v0 = fmaxf(c[mt][nt][0] + bb.x, 0.f);
                        float v1 = fmaxf(c[mt][nt][1] + bb.y, 0.f);
                        float v2 = fmaxf(c[mt][nt][2] + bb.x, 0.f);
                        float v3 = fmaxf(c[mt][nt][3] + bb.y, 0.f);
                        *(uint32_t*)(act + r0 * ROWB + n0 * 2) = pack_h2(v0, v1);
                        *(uint32_t*)(act + (r0 + 8) * ROWB + n0 * 2) = pack_h2(v2, v3);
                    }
                }
                __syncwarp();
            } else {
                // final layer: write pre-activation last_feat, compute output head
                const float* bia = sbias + 7 * 128;
                float* out2 = out + (size_t)NPTS * 3;
                float hs[2][2][3];
#pragma unroll
                for (int mt = 0; mt < 2; ++mt)
#pragma unroll
                    for (int rr = 0; rr < 2; ++rr)
#pragma unroll
                        for (int cc = 0; cc < 3; ++cc) hs[mt][rr][cc] = 0.f;
#pragma unroll
                for (int nt = 0; nt < 16; ++nt) {
                    const int n0 = nt * 8 + (lane & 3) * 2;
                    float2 bb = *reinterpret_cast<const float2*>(bia + n0);
#pragma unroll
                    for (int mt = 0; mt < 2; ++mt) {
                        const int r0 = mrow + mt * 16 + (lane >> 2);
                        float pre0 = c[mt][nt][0] + bb.x;
                        float pre1 = c[mt][nt][1] + bb.y;
                        float pre2 = c[mt][nt][2] + bb.x;
                        float pre3 = c[mt][nt][3] + bb.y;
                        *(float2*)(out2 + (size_t)(bp0 + r0) * HID + n0) = make_float2(pre0, pre1);
                        *(float2*)(out2 + (size_t)(bp0 + r0 + 8) * HID + n0) = make_float2(pre2, pre3);
                        float a0 = fmaxf(pre0, 0.f), a1 = fmaxf(pre1, 0.f);
                        float a2 = fmaxf(pre2, 0.f), a3 = fmaxf(pre3, 0.f);
#pragma unroll
                        for (int cc = 0; cc < 3; ++cc) {
                            hs[mt][0][cc] = fmaf(a0, swout[cc * 128 + n0], hs[mt][0][cc]);
                            hs[mt][0][cc] = fmaf(a1, swout[cc * 128 + n0 + 1], hs[mt][0][cc]);
                            hs[mt][1][cc] = fmaf(a2, swout[cc * 128 + n0], hs[mt][1][cc]);
                            hs[mt][1][cc] = fmaf(a3, swout[cc * 128 + n0 + 1], hs[mt][1][cc]);
                        }
                    }
                }
#pragma unroll
                for (int mt = 0; mt < 2; ++mt)
#pragma unroll
                    for (int rr = 0; rr < 2; ++rr)
#pragma unroll
                        for (int cc = 0; cc < 3; ++cc) {
                            float v = hs[mt][rr][cc];
                            v += __shfl_xor_sync(0xffffffffu, v, 1);
                            v += __shfl_xor_sync(0xffffffffu, v, 2);
                            hs[mt][rr][cc] = v;
                        }
                if ((lane & 3) == 0) {
#pragma unroll
                    for (int mt = 0; mt < 2; ++mt)
#pragma unroll
                        for (int rr = 0; rr < 2; ++rr) {
                            const int r = mrow + mt * 16 + (lane >> 2) + rr * 8;
                            const int gp = bp0 + r;
#pragma unroll
                            for (int cc = 0; cc < 3; ++cc)
                                out[gp * 3 + cc] = pts[gp * 3 + cc] + g_gshift[gp * 3 + cc]
                                                   + hs[mt][rr][cc] + sbout[cc];
                        }
                }
            }
        }
        __syncthreads();  // protect buf[st&1] before it is refilled at iter st+1
    }
}

// ---------------------------------------------------------------------------
extern "C" void kernel_launch(void* const* d_in, const int* in_sizes, int n_in,
                              void* d_out, int out_size) {
    const float* pts      = (const float*)d_in[0];
    const float* deformed = (const float*)d_in[1];
    const float* cano     = (const float*)d_in[2];
    const float* latent   = (const float*)d_in[3];
    const float* w[8];
    const float* b[8];
    for (int i = 0; i < 8; ++i) {
        w[i] = (const float*)d_in[4 + 2 * i];
        b[i] = (const float*)d_in[5 + 2 * i];
    }
    const float* w_out = (const float*)d_in[20];
    const float* b_out = (const float*)d_in[21];
    float* out = (float*)d_out;

    const int smem_nn = VV * 16;
    cudaFuncSetAttribute(nn_kernel, cudaFuncAttributeMaxDynamicSharedMemorySize, smem_nn);
    cudaFuncSetAttribute(mlp_mma_kernel, cudaFuncAttributeMaxDynamicSharedMemorySize, SMEM_MLP);

    prep_wfrag<<<72, 256>>>(w[0], w[1], w[2], w[3], w[4], w[5], w[6], w[7]);
    nn_kernel<<<NPTS / 512, 256, smem_nn>>>(pts, deformed, cano);
    mlp_mma_kernel<<<NPTS / 128, 128, SMEM_MLP>>>(pts, latent, b[0], b[1], b[2], b[3], b[4],
                                                  b[5], b[6], b[7], w_out, b_out, out);
}

// round 16
// speedup vs baseline: 1.8772x; 1.2368x over previous
#include <cuda_runtime.h>
#include <cuda_fp16.h>
#include <cstdint>

#define BB 2
#define PP 32768
#define VV 5023
#define VV4 5024          // padded to multiple of 4
#define LAT 32
#define HID 128
#define NPTS (BB*PP)
#define NSUB 9
#define ROWB 272          // bytes per activation row (128 fp16 + 16B pad -> conflict-free ldmatrix)

// Weight fragments (fp16, single product), uint4-paired: [s][ks][np][lane]
__device__ uint4 g_wfrag[NSUB * 8 * 8 * 32];
__device__ float g_gshift[NPTS * 3];

// ---------------------------------------------------------------------------
// NN search + gshift, with prep_wfrag fused into the prologue.
// Inner loop: min-tree over 4 vertices + lazy group index (recovered exactly
// after the loop). 256 threads, 2 points/thread.
// ---------------------------------------------------------------------------
__device__ __forceinline__ float score3(float4 q, float x, float y, float z) {
    return __fmaf_rn(-q.x, x, __fmaf_rn(-q.y, y, __fmaf_rn(-q.z, z, q.w)));
}

__global__ void nn_kernel(const float* __restrict__ pts,
                          const float* __restrict__ deformed,
                          const float* __restrict__ cano,
                          const float* __restrict__ w0, const float* __restrict__ w1,
                          const float* __restrict__ w2, const float* __restrict__ w3,
                          const float* __restrict__ w4, const float* __restrict__ w5,
                          const float* __restrict__ w6, const float* __restrict__ w7) {
    extern __shared__ float4 sv[];

    // ---- fused weight prep (independent of NN work) ----
    {
        int idx = blockIdx.x * blockDim.x + threadIdx.x;
        if (idx < NSUB * 8 * 8 * 32) {
            int lane = idx & 31;
            int np = (idx >> 5) & 7;
            int ks = (idx >> 8) & 7;
            int s  = idx >> 11;
            const float* w; int Ktot, k0, valid;
            switch (s) {
                case 0: w = w0; Ktot = 110; k0 = 0;   valid = 110; break;
                case 1: w = w1; Ktot = 128; k0 = 0;   valid = 128; break;
                case 2: w = w2; Ktot = 128; k0 = 0;   valid = 128; break;
                case 3: w = w3; Ktot = 128; k0 = 0;   valid = 128; break;
                case 4: w = w4; Ktot = 238; k0 = 0;   valid = 110; break;   // l4 init part
                case 5: w = w4; Ktot = 238; k0 = 110; valid = 128; break;   // l4 hidden part
                case 6: w = w5; Ktot = 128; k0 = 0;   valid = 128; break;
                case 7: w = w6; Ktot = 128; k0 = 0;   valid = 128; break;
                default: w = w7; Ktot = 128; k0 = 0;  valid = 128; break;
            }
            uint32_t frag[2][2];
#pragma unroll
            for (int d = 0; d < 2; ++d) {
                int nt = 2 * np + d;
                int n = nt * 8 + (lane >> 2);
                int kb = ks * 16 + (lane & 3) * 2;
                unsigned short v16[4];
#pragma unroll
                for (int j = 0; j < 4; ++j) {
                    int kk = kb + (j & 1) + (j >> 1) * 8;
                    float v = (kk < valid) ? w[n * Ktot + k0 + kk] : 0.f;
                    v16[j] = __half_as_ushort(__float2half_rn(v));
                }
                frag[d][0] = (uint32_t)v16[0] | ((uint32_t)v16[1] << 16);
                frag[d][1] = (uint32_t)v16[2] | ((uint32_t)v16[3] << 16);
            }
            g_wfrag[idx] = make_uint4(frag[0][0], frag[0][1], frag[1][0], frag[1][1]);
        }
    }

    // ---- stage vertices ----
    const int blockBase = blockIdx.x * 512;
    const int b = blockBase / PP;
    const float* dv = deformed + (size_t)b * VV * 3;
    for (int v = threadIdx.x; v < VV; v += 256) {
        float x = dv[3 * v + 0], y = dv[3 * v + 1], z = dv[3 * v + 2];
        sv[v] = make_float4(x, y, z, 0.5f * (x * x + y * y + z * z));
    }
    if (threadIdx.x == 0) sv[VV] = make_float4(0.f, 0.f, 0.f, 1e30f);  // pad
    __syncthreads();

    const int pA = blockBase + threadIdx.x;
    const int pB = pA + 256;
    float ax = pts[pA * 3 + 0], ay = pts[pA * 3 + 1], az = pts[pA * 3 + 2];
    float bx = pts[pB * 3 + 0], by = pts[pB * 3 + 1], bz = pts[pB * 3 + 2];

    float bsA = 1e30f, bsB = 1e30f;
    int gA = 0, gB = 0;
#pragma unroll 2
    for (int v = 0; v < VV4; v += 4) {
        float4 q0 = sv[v + 0], q1 = sv[v + 1], q2 = sv[v + 2], q3 = sv[v + 3];
        float a0 = score3(q0, ax, ay, az), a1 = score3(q1, ax, ay, az);
        float a2 = score3(q2, ax, ay, az), a3 = score3(q3, ax, ay, az);
        float c0 = score3(q0, bx, by, bz), c1 = score3(q1, bx, by, bz);
        float c2 = score3(q2, bx, by, bz), c3 = score3(q3, bx, by, bz);
        float mA = fminf(fminf(a0, a1), fminf(a2, a3));
        float mB = fminf(fminf(c0, c1), fminf(c2, c3));
        gA = (mA < bsA) ? v : gA;
        bsA = fminf(bsA, mA);
        gB = (mB < bsB) ? v : gB;
        bsB = fminf(bsB, mB);
    }
    // exact index recovery within the winning group (bit-identical recompute)
    int iA, iB;
    {
        float4 q0 = sv[gA + 0], q1 = sv[gA + 1], q2 = sv[gA + 2], q3 = sv[gA + 3];
        float a0 = score3(q0, ax, ay, az), a1 = score3(q1, ax, ay, az);
        float a2 = score3(q2, ax, ay, az);
        iA = gA + ((a0 == bsA) ? 0 : (a1 == bsA) ? 1 : (a2 == bsA) ? 2 : 3);
    }
    {
        float4 q0 = sv[gB + 0], q1 = sv[gB + 1], q2 = sv[gB + 2], q3 = sv[gB + 3];
        float c0 = score3(q0, bx, by, bz), c1 = score3(q1, bx, by, bz);
        float c2 = score3(q2, bx, by, bz);
        iB = gB + ((c0 == bsB) ? 0 : (c1 == bsB) ? 1 : (c2 == bsB) ? 2 : 3);
    }
    {
        float p2 = __fmaf_rn(ax, ax, __fmaf_rn(ay, ay, az * az));
        float w = __expf(-fmaxf(__fmaf_rn(2.f, bsA, p2), 0.f));
        float4 q = sv[iA];
        g_gshift[pA * 3 + 0] = (cano[iA * 3 + 0] - q.x) * w;
        g_gshift[pA * 3 + 1] = (cano[iA * 3 + 1] - q.y) * w;
        g_gshift[pA * 3 + 2] = (cano[iA * 3 + 2] - q.z) * w;
    }
    {
        float p2 = __fmaf_rn(bx, bx, __fmaf_rn(by, by, bz * bz));
        float w = __expf(-fmaxf(__fmaf_rn(2.f, bsB, p2), 0.f));
        float4 q = sv[iB];
        g_gshift[pB * 3 + 0] = (cano[iB * 3 + 0] - q.x) * w;
        g_gshift[pB * 3 + 1] = (cano[iB * 3 + 1] - q.y) * w;
        g_gshift[pB * 3 + 2] = (cano[iB * 3 + 2] - q.z) * w;
    }
}

// ---------------------------------------------------------------------------
// helpers
// ---------------------------------------------------------------------------
__device__ __forceinline__ uint32_t smem_u32(const void* p) {
    uint32_t a;
    asm("{ .reg .u64 t; cvta.to.shared.u64 t, %1; cvt.u32.u64 %0, t; }" : "=r"(a) : "l"(p));
    return a;
}
#define CP_ASYNC16(dst, src) \
    asm volatile("cp.async.cg.shared.global [%0], [%1], 16;" :: "r"(dst), "l"(src))
#define CP_COMMIT() asm volatile("cp.async.commit_group;" ::: "memory")
#define CP_WAIT1()  asm volatile("cp.async.wait_group 1;" ::: "memory")
#define CP_WAIT0()  asm volatile("cp.async.wait_group 0;" ::: "memory")

__device__ __forceinline__ void ldmA(uint32_t a[4], uint32_t su, int rowbase, int kbase, int lane) {
    int grp = lane >> 3, ri = lane & 7;
    int row = rowbase + ri + ((grp & 1) << 3);
    int col = kbase + ((grp & 2) << 2);
    uint32_t addr = su + (uint32_t)(row * ROWB + col * 2);
    asm volatile("ldmatrix.sync.aligned.m8n8.x4.shared.b16 {%0,%1,%2,%3}, [%4];"
                 : "=r"(a[0]), "=r"(a[1]), "=r"(a[2]), "=r"(a[3]) : "r"(addr));
}
__device__ __forceinline__ void mma16816(float c[4], const uint32_t a[4], uint32_t b0, uint32_t b1) {
    asm volatile(
        "mma.sync.aligned.m16n8k16.row.col.f32.f16.f16.f32 "
        "{%0,%1,%2,%3},{%4,%5,%6,%7},{%8,%9},{%0,%1,%2,%3};"
        : "+f"(c[0]), "+f"(c[1]), "+f"(c[2]), "+f"(c[3])
        : "r"(a[0]), "r"(a[1]), "r"(a[2]), "r"(a[3]), "r"(b0), "r"(b1));
}
__device__ __forceinline__ uint32_t pack_h2(float lo, float hi) {
    __half2 h = __floats2half2_rn(lo, hi);
    return *reinterpret_cast<uint32_t*>(&h);
}

// ---------------------------------------------------------------------------
// feature build (one point per thread) -> single fp16 buffer
// ---------------------------------------------------------------------------
__device__ void build_feat(char* act, int row, int bp,
                           const float* __restrict__ pts, const float* __restrict__ latent) {
    __half* a = (__half*)(act + row * ROWB);
    float px = pts[bp * 3 + 0], py = pts[bp * 3 + 1], pz = pts[bp * 3 + 2];
    float gx = g_gshift[bp * 3 + 0], gy = g_gshift[bp * 3 + 1], gz = g_gshift[bp * 3 + 2];
    a[0] = __float2half_rn(px); a[1] = __float2half_rn(py); a[2] = __float2half_rn(pz);
#pragma unroll
    for (int l = 0; l < 10; ++l) {
        float f = (float)(1 << l);
        float s, c;
        __sincosf(px * f, &s, &c); a[3 + 6 * l + 0] = __float2half_rn(s); a[3 + 6 * l + 3] = __float2half_rn(c);
        __sincosf(py * f, &s, &c); a[3 + 6 * l + 1] = __float2half_rn(s); a[3 + 6 * l + 4] = __float2half_rn(c);
        __sincosf(pz * f, &s, &c); a[3 + 6 * l + 2] = __float2half_rn(s); a[3 + 6 * l + 5] = __float2half_rn(c);
    }
    a[63] = __float2half_rn(gx); a[64] = __float2half_rn(gy); a[65] = __float2half_rn(gz);
#pragma unroll
    for (int l = 0; l < 2; ++l) {
        float f = (float)(1 << l);
        float s, c;
        __sincosf(gx * f, &s, &c); a[66 + 6 * l + 0] = __float2half_rn(s); a[66 + 6 * l + 3] = __float2half_rn(c);
        __sincosf(gy * f, &s, &c); a[66 + 6 * l + 1] = __float2half_rn(s); a[66 + 6 * l + 4] = __float2half_rn(c);
        __sincosf(gz * f, &s, &c); a[66 + 6 * l + 2] = __float2half_rn(s); a[66 + 6 * l + 5] = __float2half_rn(c);
    }
#pragma unroll
    for (int j = 0; j < 32; ++j) a[78 + j] = __float2half_rn(latent[(size_t)bp * LAT + j]);
    __half z = __float2half_rn(0.f);
#pragma unroll
    for (int j = 110; j < 128; ++j) a[j] = z;
}

// ---------------------------------------------------------------------------
// SMEM layout (128-thread CTA, 128 points) -> 2 CTAs/SM
// Double-buffered 32KB weight stages.
// ---------------------------------------------------------------------------
#define OFF_A    0
#define OFF_W0   34816
#define OFF_W1   67584
#define OFF_BIAS 100352
#define OFF_WOUT 104448
#define OFF_BOUT 105984
#define SMEM_MLP 106000

__global__ void __launch_bounds__(128, 2)
mlp_mma_kernel(const float* __restrict__ pts, const float* __restrict__ latent,
               const float* __restrict__ b0, const float* __restrict__ b1,
               const float* __restrict__ b2, const float* __restrict__ b3,
               const float* __restrict__ b4, const float* __restrict__ b5,
               const float* __restrict__ b6, const float* __restrict__ b7,
               const float* __restrict__ w_out, const float* __restrict__ b_out,
               float* __restrict__ out) {
    extern __shared__ char sm[];
    char* act = sm + OFF_A;
    float* sbias = (float*)(sm + OFF_BIAS);
    float* swout = (float*)(sm + OFF_WOUT);
    float* sbout = (float*)(sm + OFF_BOUT);

    const int tid = threadIdx.x;
    const int wid = tid >> 5;
    const int lane = tid & 31;
    const int bp0 = blockIdx.x * 128;
    const int bp = bp0 + tid;
    const uint32_t suA = smem_u32(act);
    const uint32_t suW[2] = {smem_u32(sm + OFF_W0), smem_u32(sm + OFF_W1)};
    const int mrow = wid * 32;

    // step tables
    const int stepS[NSUB]    = {0, 1, 2, 3, 5, 4, 6, 7, 8};
    const int stepZero[NSUB] = {1, 1, 1, 1, 1, 0, 1, 1, 1};
    const int stepEpi[NSUB]  = {0, 1, 2, 3, -1, 4, 5, 6, 7};
    const int stepReb[NSUB]  = {0, 0, 0, 0, 0, 1, 0, 0, 0};

    // prologue: prefetch L0 into buf0 (32KB = 2048 uint4, 16 per thread)
    {
        const char* src = (const char*)(g_wfrag + (size_t)stepS[0] * 2048);
#pragma unroll
        for (int i = 0; i < 16; ++i) {
            uint32_t off = (uint32_t)(tid + 128 * i) * 16u;
            CP_ASYNC16(suW[0] + off, src + off);
        }
        CP_COMMIT();
    }

    // stage biases / head weights
    {
        const float* bs[8] = {b0, b1, b2, b3, b4, b5, b6, b7};
        for (int i = tid; i < 1024; i += 128) sbias[i] = bs[i >> 7][i & 127];
        for (int i = tid; i < 384; i += 128) swout[i] = w_out[i];
        if (tid < 3) sbout[tid] = b_out[tid];
    }

    build_feat(act, tid, bp, pts, latent);

    float c[2][16][4];

#pragma unroll 1
    for (int st = 0; st < NSUB; ++st) {
        // prefetch next layer into the other buffer, then wait for this layer
        if (st + 1 < NSUB) {
            const char* src = (const char*)(g_wfrag + (size_t)stepS[st + 1] * 2048);
            uint32_t dst = suW[(st + 1) & 1];
#pragma unroll
            for (int i = 0; i < 16; ++i) {
                uint32_t off = (uint32_t)(tid + 128 * i) * 16u;
                CP_ASYNC16(dst + off, src + off);
            }
            CP_COMMIT();
            CP_WAIT1();
        } else {
            CP_WAIT0();
        }
        __syncthreads();

        if (stepZero[st]) {
#pragma unroll
            for (int mt = 0; mt < 2; ++mt)
#pragma unroll
                for (int nt = 0; nt < 16; ++nt)
#pragma unroll
                    for (int j = 0; j < 4; ++j) c[mt][nt][j] = 0.f;
        }
        if (stepReb[st]) {
            build_feat(act, tid, bp, pts, latent);
            __syncwarp();
        }

        // ---- software-pipelined MMA: B-register rotation + A prefetch ----
        {
            const char* wbuf = sm + (((st & 1) == 0) ? OFF_W0 : OFF_W1);
            uint32_t a0[4], a1[4];
            ldmA(a0, suA, mrow, 0, lane);
            ldmA(a1, suA, mrow + 16, 0, lane);
            uint4 B = *reinterpret_cast<const uint4*>(wbuf + (uint32_t)(0 * 32 + lane) * 16u);
#pragma unroll
            for (int i = 0; i < 64; ++i) {
                const int np = i & 7;
                const int ks = i >> 3;
                uint4 Bn;
                if (i < 63)
                    Bn = *reinterpret_cast<const uint4*>(wbuf + (uint32_t)((i + 1) * 32 + lane) * 16u);
                uint32_t a0n[4], a1n[4];
                if (np == 7 && ks < 7) {
                    ldmA(a0n, suA, mrow, (ks + 1) * 16, lane);
                    ldmA(a1n, suA, mrow + 16, (ks + 1) * 16, lane);
                }
                mma16816(c[0][2 * np], a0, B.x, B.y);
                mma16816(c[1][2 * np], a1, B.x, B.y);
                mma16816(c[0][2 * np + 1], a0, B.z, B.w);
                mma16816(c[1][2 * np + 1], a1, B.z, B.w);
                if (i < 63) B = Bn;
                if (np == 7 && ks < 7) {
#pragma unroll
                    for (int j = 0; j < 4; ++j) { a0[j] = a0n[j]; a1[j] = a1n[j]; }
                }
            }
        }

        const int l = stepEpi[st];
        if (l >= 0) {
            __syncwarp();
            if (l < 7) {
                const float* bia = sbias + l * 128;
#pragma unroll
                for (int nt = 0; nt < 16; ++nt) {
                    const int n0 = nt * 8 + (lane & 3) * 2;
                    float2 bb = *reinterpret_cast<const float2*>(bia + n0);
#pragma unroll
                    for (int mt = 0; mt < 2; ++mt) {
                        const int r0 = mrow + mt * 16 + (lane >> 2);
                        float v0 = fmaxf(c[mt][nt][0] + bb.x, 0.f);
                        float v1 = fmaxf(c[mt][nt][1] + bb.y, 0.f);
                        float v2 = fmaxf(c[mt][nt][2] + bb.x, 0.f);
                        float v3 = fmaxf(c[mt][nt][3] + bb.y, 0.f);
                        *(uint32_t*)(act + r0 * ROWB + n0 * 2) = pack_h2(v0, v1);
                        *(uint32_t*)(act + (r0 + 8) * ROWB + n0 * 2) = pack_h2(v2, v3);
                    }
                }
                __syncwarp();
            } else {
                // final layer: write pre-activation last_feat, compute output head
                const float* bia = sbias + 7 * 128;
                float* out2 = out + (size_t)NPTS * 3;
                float hs[2][2][3];
#pragma unroll
                for (int mt = 0; mt < 2; ++mt)
#pragma unroll
                    for (int rr = 0; rr < 2; ++rr)
#pragma unroll
                        for (int cc = 0; cc < 3; ++cc) hs[mt][rr][cc] = 0.f;
#pragma unroll
                for (int nt = 0; nt < 16; ++nt) {
                    const int n0 = nt * 8 + (lane & 3) * 2;
                    float2 bb = *reinterpret_cast<const float2*>(bia + n0);
#pragma unroll
                    for (int mt = 0; mt < 2; ++mt) {
                        const int r0 = mrow + mt * 16 + (lane >> 2);
                        float pre0 = c[mt][nt][0] + bb.x;
                        float pre1 = c[mt][nt][1] + bb.y;
                        float pre2 = c[mt][nt][2] + bb.x;
                        float pre3 = c[mt][nt][3] + bb.y;
                        *(float2*)(out2 + (size_t)(bp0 + r0) * HID + n0) = make_float2(pre0, pre1);
                        *(float2*)(out2 + (size_t)(bp0 + r0 + 8) * HID + n0) = make_float2(pre2, pre3);
                        float a0 = fmaxf(pre0, 0.f), a1 = fmaxf(pre1, 0.f);
                        float a2 = fmaxf(pre2, 0.f), a3 = fmaxf(pre3, 0.f);
#pragma unroll
                        for (int cc = 0; cc < 3; ++cc) {
                            hs[mt][0][cc] = fmaf(a0, swout[cc * 128 + n0], hs[mt][0][cc]);
                            hs[mt][0][cc] = fmaf(a1, swout[cc * 128 + n0 + 1], hs[mt][0][cc]);
                            hs[mt][1][cc] = fmaf(a2, swout[cc * 128 + n0], hs[mt][1][cc]);
                            hs[mt][1][cc] = fmaf(a3, swout[cc * 128 + n0 + 1], hs[mt][1][cc]);
                        }
                    }
                }
#pragma unroll
                for (int mt = 0; mt < 2; ++mt)
#pragma unroll
                    for (int rr = 0; rr < 2; ++rr)
#pragma unroll
                        for (int cc = 0; cc < 3; ++cc) {
                            float v = hs[mt][rr][cc];
                            v += __shfl_xor_sync(0xffffffffu, v, 1);
                            v += __shfl_xor_sync(0xffffffffu, v, 2);
                            hs[mt][rr][cc] = v;
                        }
                if ((lane & 3) == 0) {
#pragma unroll
                    for (int mt = 0; mt < 2; ++mt)
#pragma unroll
                        for (int rr = 0; rr < 2; ++rr) {
                            const int r = mrow + mt * 16 + (lane >> 2) + rr * 8;
                            const int gp = bp0 + r;
#pragma unroll
                            for (int cc = 0; cc < 3; ++cc)
                                out[gp * 3 + cc] = pts[gp * 3 + cc] + g_gshift[gp * 3 + cc]
                                                   + hs[mt][rr][cc] + sbout[cc];
                        }
                }
            }
        }
        __syncthreads();  // protect buf[st&1] before it is refilled at iter st+1
    }
}

// ---------------------------------------------------------------------------
extern "C" void kernel_launch(void* const* d_in, const int* in_sizes, int n_in,
                              void* d_out, int out_size) {
    const float* pts      = (const float*)d_in[0];
    const float* deformed = (const float*)d_in[1];
    const float* cano     = (const float*)d_in[2];
    const float* latent   = (const float*)d_in[3];
    const float* w[8];
    const float* b[8];
    for (int i = 0; i < 8; ++i) {
        w[i] = (const float*)d_in[4 + 2 * i];
        b[i] = (const float*)d_in[5 + 2 * i];
    }
    const float* w_out = (const float*)d_in[20];
    const float* b_out = (const float*)d_in[21];
    float* out = (float*)d_out;

    const int smem_nn = VV4 * 16;  // 80384
    cudaFuncSetAttribute(nn_kernel, cudaFuncAttributeMaxDynamicSharedMemorySize, smem_nn);
    cudaFuncSetAttribute(mlp_mma_kernel, cudaFuncAttributeMaxDynamicSharedMemorySize, SMEM_MLP);

    nn_kernel<<<NPTS / 512, 256, smem_nn>>>(pts, deformed, cano,
                                            w[0], w[1], w[2], w[3], w[4], w[5], w[6], w[7]);
    mlp_mma_kernel<<<NPTS / 128, 128, SMEM_MLP>>>(pts, latent, b[0], b[1], b[2], b[3], b[4],
                                                  b[5], b[6], b[7], w_out, b_out, out);
}